// round 15
// baseline (speedup 1.0000x reference)
#include <cuda_runtime.h>
#include <cuda_fp16.h>
#include <cstdint>

// ---------------------------------------------------------------------------
// SimpleGCN on B200, round 15: R12 base (283us) + gather/gemm FUSION.
//   gemm(L+1) row i needs only gather-L row i -> fuse them: gather row into
//   smem (fp32), apply lrelu, gemm against smem W, emit fp16 h. Kills two
//   kernel boundaries and the 2x25.6MB fp32 acc round-trip per middle layer.
//   Gather inner loop = byte-identical R12 (R11/R13/R14 restructures all
//   regressed). Ping-pong h buffers (g_h -> g_hB -> g_h).
//   Launches: prep0(0) deg(1) alloc(2) fill(3<-profiled) gemm1(4)
//             fused2(5) fused3(6) gather3(7)
// ---------------------------------------------------------------------------

#define MAXN (1 << 17)
#define MAXE (1 << 21)
#define FDIM 64
#define XSTRIDE 68   // padded smem row stride (floats) to avoid bank conflicts

__device__ __half g_h [(size_t)MAXN * FDIM];
__device__ __half g_hB[(size_t)MAXN * FDIM];
__device__ float  g_dinv[MAXN];
__device__ int    g_cnt[MAXN];
__device__ int    g_row[MAXN];
__device__ int    g_cur[MAXN];
__device__ int    g_total;
__device__ int2   g_edata[MAXE];
__device__ int    g_is64;

// --- packed f32x2 helpers ---
__device__ __forceinline__ unsigned long long ffma2(
    unsigned long long a, unsigned long long b, unsigned long long c) {
    unsigned long long d;
    asm("fma.rn.f32x2 %0, %1, %2, %3;" : "=l"(d) : "l"(a), "l"(b), "l"(c));
    return d;
}
__device__ __forceinline__ unsigned long long pack2(float x) {
    unsigned long long p;
    asm("mov.b64 %0, {%1, %1};" : "=l"(p) : "f"(x));
    return p;
}
__device__ __forceinline__ float2 unpack2(unsigned long long p) {
    float lo, hi;
    asm("mov.b64 {%0, %1}, %2;" : "=f"(lo), "=f"(hi) : "l"(p));
    return make_float2(lo, hi);
}
__device__ __forceinline__ uint32_t h2_as_u32(__half2 v) {
    return *reinterpret_cast<uint32_t*>(&v);
}

// --- launch 0: dtype detect + zero counters
__global__ void k_prep0(const unsigned int* __restrict__ w, long long nwords, int n) {
    int i = blockIdx.x * blockDim.x + threadIdx.x;
    if (i < n) { g_cnt[i] = 0; g_cur[i] = 0; }
    if (i == 0) g_total = 0;
    if (blockIdx.x == 0) {
        __shared__ int cnt;
        if (threadIdx.x == 0) cnt = 0;
        __syncthreads();
        int zeros = 0;
        for (long long j = threadIdx.x; j < 2048 && j < nwords; j += blockDim.x)
            if ((j & 1) && w[j] == 0u) zeros++;
        atomicAdd(&cnt, zeros);
        __syncthreads();
        if (threadIdx.x == 0) g_is64 = (cnt > 512) ? 1 : 0;
    }
}

__device__ __forceinline__ int load_idx(const void* e, long long pos) {
    if (g_is64) return (int)((const long long*)e)[pos];
    return ((const int*)e)[pos];
}

// --- launch 1: in-degree histogram
__global__ void k_deg(const void* __restrict__ e, long long E) {
    long long i = (long long)blockIdx.x * blockDim.x + threadIdx.x;
    if (i >= E) return;
    atomicAdd(&g_cnt[load_idx(e, E + i)], 1);
}

// --- launch 2: dinv + unordered disjoint CSR range allocation
__global__ void k_dinv_alloc(int n) {
    int i = blockIdx.x * blockDim.x + threadIdx.x;
    if (i >= n) return;
    int c = g_cnt[i];
    g_dinv[i] = rsqrtf((float)(1 + c));   // +1 self loop
    g_row[i] = atomicAdd(&g_total, c);
}

// --- launch 3: CSR fill {src, norm}   <- profiled slot (canary: ~35.5us)
__global__ void k_fill(const void* __restrict__ e, long long E) {
    long long i = (long long)blockIdx.x * blockDim.x + threadIdx.x;
    if (i >= E) return;
    int s, d;
    if (g_is64) {
        const long long* p = (const long long*)e;
        s = (int)p[i]; d = (int)p[E + i];
    } else {
        const int* p = (const int*)e;
        s = p[i]; d = p[E + i];
    }
    int pos = g_row[d] + atomicAdd(&g_cur[d], 1);
    g_edata[pos] = make_int2(s, __float_as_int(g_dinv[s] * g_dinv[d]));
}

// --- launch 4: standalone GEMM (layer 1 only): h = x @ W1, fp16 epilogue
__global__ void __launch_bounds__(128)
k_gemm1(const float* __restrict__ in, const float* __restrict__ W,
        __half* __restrict__ h, int n) {
    __shared__ float Ws[FDIM * FDIM];
    for (int i = threadIdx.x; i < FDIM * FDIM; i += blockDim.x) Ws[i] = W[i];
    __syncthreads();

    int r = blockIdx.x * blockDim.x + threadIdx.x;
    if (r >= n) return;

    unsigned long long acc2[FDIM / 2];
#pragma unroll
    for (int j = 0; j < FDIM / 2; j++) acc2[j] = 0ull;

    const float4* x4 = (const float4*)(in + (size_t)r * FDIM);
#pragma unroll 4
    for (int k4 = 0; k4 < FDIM / 4; k4++) {
        float4 xv = __ldg(x4 + k4);
        float xs[4] = {xv.x, xv.y, xv.z, xv.w};
#pragma unroll
        for (int kk = 0; kk < 4; kk++) {
            unsigned long long xk2 = pack2(xs[kk]);
            const ulonglong2* Wr = (const ulonglong2*)&Ws[(k4 * 4 + kk) * FDIM];
#pragma unroll
            for (int j = 0; j < FDIM / 4; j++) {
                ulonglong2 w2 = Wr[j];
                acc2[2 * j]     = ffma2(xk2, w2.x, acc2[2 * j]);
                acc2[2 * j + 1] = ffma2(xk2, w2.y, acc2[2 * j + 1]);
            }
        }
    }

    uint4* hr = (uint4*)(h + (size_t)r * FDIM);
#pragma unroll
    for (int j = 0; j < 8; j++) {
        float2 p0 = unpack2(acc2[4 * j + 0]);
        float2 p1 = unpack2(acc2[4 * j + 1]);
        float2 p2 = unpack2(acc2[4 * j + 2]);
        float2 p3 = unpack2(acc2[4 * j + 3]);
        uint4 v;
        v.x = h2_as_u32(__floats2half2_rn(p0.x, p0.y));
        v.y = h2_as_u32(__floats2half2_rn(p1.x, p1.y));
        v.z = h2_as_u32(__floats2half2_rn(p2.x, p2.y));
        v.w = h2_as_u32(__floats2half2_rn(p3.x, p3.y));
        hr[j] = v;
    }
}

// --- gather core (R12 loop, unchanged): returns row slab for (node, l16)
__device__ __forceinline__ void acc_u2(uint2 u, float nn, float4& a) {
    __half2 h0 = *reinterpret_cast<__half2*>(&u.x);
    __half2 h1 = *reinterpret_cast<__half2*>(&u.y);
    float2 f0 = __half22float2(h0);
    float2 f1 = __half22float2(h1);
    a.x = fmaf(f0.x, nn, a.x); a.y = fmaf(f0.y, nn, a.y);
    a.z = fmaf(f1.x, nn, a.z); a.w = fmaf(f1.y, nn, a.w);
}

__device__ __forceinline__ float4 gather_row(
    const uint2* __restrict__ h2, const float* __restrict__ b,
    int node, int l16) {
    int start = g_row[node];
    int deg   = g_cnt[node];
    float di  = g_dinv[node];
    float sn  = di * di;

    float4 a = __ldg((const float4*)b + l16);
    acc_u2(h2[(size_t)node * 16 + l16], sn, a);   // self loop

    const int2* ed = g_edata + start;
    int e = 0;
    for (; e + 4 <= deg; e += 4) {
        int2 e0 = ed[e], e1 = ed[e + 1], e2 = ed[e + 2], e3 = ed[e + 3];
        uint2 v0 = h2[(size_t)e0.x * 16 + l16];
        uint2 v1 = h2[(size_t)e1.x * 16 + l16];
        uint2 v2 = h2[(size_t)e2.x * 16 + l16];
        uint2 v3 = h2[(size_t)e3.x * 16 + l16];
        acc_u2(v0, __int_as_float(e0.y), a);
        acc_u2(v1, __int_as_float(e1.y), a);
        acc_u2(v2, __int_as_float(e2.y), a);
        acc_u2(v3, __int_as_float(e3.y), a);
    }
    for (; e < deg; e++) {
        int2 ee = ed[e];
        uint2 v = h2[(size_t)ee.x * 16 + l16];
        acc_u2(v, __int_as_float(ee.y), a);
    }
    return a;
}

// --- launches 5,6: FUSED gather(L) + lrelu + gemm(L+1) -> fp16 h_out
//     256 threads = 16 nodes; lane l16 owns 4 cols in both phases.
__global__ void __launch_bounds__(256)
k_fused(const __half* __restrict__ hin, const float* __restrict__ b,
        const float* __restrict__ W, __half* __restrict__ hout, int n) {
    __shared__ float Ws[FDIM * FDIM];          // 16 KB
    __shared__ float sx[16][XSTRIDE];          // gathered rows (padded)

    for (int i = threadIdx.x; i < FDIM * FDIM; i += blockDim.x) Ws[i] = W[i];

    int local = threadIdx.x >> 4;
    int l16   = threadIdx.x & 15;
    int node  = blockIdx.x * 16 + local;
    bool valid = node < n;

    if (valid) {
        float4 a = gather_row((const uint2*)hin, b, node, l16);
        *(float4*)&sx[local][4 * l16] = a;
    }
    __syncthreads();

    if (valid) {
        int c0 = 4 * l16;
        float r0 = 0.f, r1 = 0.f, r2 = 0.f, r3 = 0.f;
#pragma unroll 8
        for (int k = 0; k < FDIM; k++) {
            float xk = sx[local][k];
            xk = xk > 0.0f ? xk : 0.01f * xk;          // leaky relu
            float4 w = *(const float4*)&Ws[k * FDIM + c0];
            r0 = fmaf(xk, w.x, r0);
            r1 = fmaf(xk, w.y, r1);
            r2 = fmaf(xk, w.z, r2);
            r3 = fmaf(xk, w.w, r3);
        }
        uint2 v;
        v.x = h2_as_u32(__floats2half2_rn(r0, r1));
        v.y = h2_as_u32(__floats2half2_rn(r2, r3));
        ((uint2*)hout)[(size_t)node * 16 + l16] = v;
    }
}

// --- launch 7: final gather (layer 3) -> fp32 out
__global__ void __launch_bounds__(256)
k_gather_out(const __half* __restrict__ hin, float* __restrict__ out,
             const float* __restrict__ b, int n) {
    int node = blockIdx.x * 16 + (threadIdx.x >> 4);
    if (node >= n) return;
    int l16 = threadIdx.x & 15;
    float4 a = gather_row((const uint2*)hin, b, node, l16);
    ((float4*)out)[(size_t)node * 16 + l16] = a;
}

extern "C" void kernel_launch(void* const* d_in, const int* in_sizes, int n_in,
                              void* d_out, int out_size) {
    const float* x  = (const float*)d_in[0];
    const void*  ei = d_in[1];
    const float* W1 = (const float*)d_in[2];
    const float* b1 = (const float*)d_in[3];
    const float* W2 = (const float*)d_in[4];
    const float* b2 = (const float*)d_in[5];
    const float* W3 = (const float*)d_in[6];
    const float* b3 = (const float*)d_in[7];
    float* out = (float*)d_out;

    int n = in_sizes[0] / FDIM;
    long long E = (long long)in_sizes[1] / 2;

    __half *hA, *hB;
    cudaGetSymbolAddress((void**)&hA, g_h);
    cudaGetSymbolAddress((void**)&hB, g_hB);

    int nb_n  = (n + 255) / 256;
    int nb_e  = (int)((E + 255) / 256);
    int nb_g  = (n + 127) / 128;
    int nb_ga = (n + 15) / 16;

    k_prep0<<<nb_n, 256>>>((const unsigned int*)ei, 2 * E, n);  // 0
    k_deg<<<nb_e, 256>>>(ei, E);                                // 1
    k_dinv_alloc<<<nb_n, 256>>>(n);                             // 2
    k_fill<<<nb_e, 256>>>(ei, E);                               // 3 <- profiled
    k_gemm1<<<nb_g, 128>>>(x, W1, hA, n);                       // 4
    k_fused<<<nb_ga, 256>>>(hA, b1, W2, hB, n);                 // 5
    k_fused<<<nb_ga, 256>>>(hB, b2, W3, hA, n);                 // 6
    k_gather_out<<<nb_ga, 256>>>(hA, out, b3, n);               // 7
}

// round 16
// speedup vs baseline: 1.0569x; 1.0569x over previous
#include <cuda_runtime.h>
#include <cuda_fp16.h>
#include <cstdint>

// ---------------------------------------------------------------------------
// SimpleGCN on B200, round 16: R12 (283us best) + block-scan range alloc.
//   R12's k_dinv_alloc did 100K atomicAdd returns on ONE address: at
//   ~0.854 cyc/op single-address L2 throughput that's ~45us serialized.
//   Replaced with smem exclusive scan + ONE atomicAdd per block (391 total).
//   Everything else byte-identical to R12 (fp16 h, 16-lane gather, ffma2
//   gemm, scan-free CSR fill with canary ~35.5us at profiled slot 3).
// ---------------------------------------------------------------------------

#define MAXN (1 << 17)
#define MAXE (1 << 21)
#define FDIM 64

__device__ __half g_h[(size_t)MAXN * FDIM];      // fp16 transformed features
__device__ float  g_acc[(size_t)MAXN * FDIM];    // fp32 layer outputs
__device__ float  g_dinv[MAXN];
__device__ int    g_cnt[MAXN];
__device__ int    g_row[MAXN];
__device__ int    g_cur[MAXN];
__device__ int    g_total;
__device__ int2   g_edata[MAXE];
__device__ int    g_is64;

// --- packed f32x2 helpers ---
__device__ __forceinline__ unsigned long long ffma2(
    unsigned long long a, unsigned long long b, unsigned long long c) {
    unsigned long long d;
    asm("fma.rn.f32x2 %0, %1, %2, %3;" : "=l"(d) : "l"(a), "l"(b), "l"(c));
    return d;
}
__device__ __forceinline__ unsigned long long pack2(float x) {
    unsigned long long p;
    asm("mov.b64 %0, {%1, %1};" : "=l"(p) : "f"(x));
    return p;
}
__device__ __forceinline__ float2 unpack2(unsigned long long p) {
    float lo, hi;
    asm("mov.b64 {%0, %1}, %2;" : "=f"(lo), "=f"(hi) : "l"(p));
    return make_float2(lo, hi);
}
__device__ __forceinline__ uint32_t h2_as_u32(__half2 v) {
    return *reinterpret_cast<uint32_t*>(&v);
}

// --- launch 0: dtype detect + zero counters
__global__ void k_prep0(const unsigned int* __restrict__ w, long long nwords, int n) {
    int i = blockIdx.x * blockDim.x + threadIdx.x;
    if (i < n) { g_cnt[i] = 0; g_cur[i] = 0; }
    if (i == 0) g_total = 0;
    if (blockIdx.x == 0) {
        __shared__ int cnt;
        if (threadIdx.x == 0) cnt = 0;
        __syncthreads();
        int zeros = 0;
        for (long long j = threadIdx.x; j < 2048 && j < nwords; j += blockDim.x)
            if ((j & 1) && w[j] == 0u) zeros++;
        atomicAdd(&cnt, zeros);
        __syncthreads();
        if (threadIdx.x == 0) g_is64 = (cnt > 512) ? 1 : 0;
    }
}

__device__ __forceinline__ int load_idx(const void* e, long long pos) {
    if (g_is64) return (int)((const long long*)e)[pos];
    return ((const int*)e)[pos];
}

// --- launch 1: in-degree histogram
__global__ void k_deg(const void* __restrict__ e, long long E) {
    long long i = (long long)blockIdx.x * blockDim.x + threadIdx.x;
    if (i >= E) return;
    atomicAdd(&g_cnt[load_idx(e, E + i)], 1);
}

// --- launch 2: dinv + disjoint range allocation via block scan.
//     ONE global atomic per block (391) instead of one per node (100K).
__global__ void k_dinv_alloc(int n) {
    __shared__ int sh[256];
    __shared__ int base;
    int i = blockIdx.x * 256 + threadIdx.x;
    int c = (i < n) ? g_cnt[i] : 0;
    if (i < n) g_dinv[i] = rsqrtf((float)(1 + c));   // +1 self loop

    sh[threadIdx.x] = c;                              // inclusive scan
    __syncthreads();
#pragma unroll
    for (int off = 1; off < 256; off <<= 1) {
        int t = (threadIdx.x >= off) ? sh[threadIdx.x - off] : 0;
        __syncthreads();
        sh[threadIdx.x] += t;
        __syncthreads();
    }
    if (threadIdx.x == 255) base = atomicAdd(&g_total, sh[255]);
    __syncthreads();
    if (i < n) g_row[i] = base + sh[threadIdx.x] - c; // exclusive + block base
}

// --- launch 3: CSR fill {src, norm}   <- profiled slot (canary: ~35.5us)
__global__ void k_fill(const void* __restrict__ e, long long E) {
    long long i = (long long)blockIdx.x * blockDim.x + threadIdx.x;
    if (i >= E) return;
    int s, d;
    if (g_is64) {
        const long long* p = (const long long*)e;
        s = (int)p[i]; d = (int)p[E + i];
    } else {
        const int* p = (const int*)e;
        s = p[i]; d = p[E + i];
    }
    int pos = g_row[d] + atomicAdd(&g_cur[d], 1);
    g_edata[pos] = make_int2(s, __float_as_int(g_dinv[s] * g_dinv[d]));
}

// --- GEMM: h = act(in) @ W via packed f32x2; fp16 epilogue
template <int LRELU>
__global__ void __launch_bounds__(128)
k_gemm(const float* __restrict__ in, const float* __restrict__ W,
       __half* __restrict__ h, int n) {
    __shared__ float Ws[FDIM * FDIM];
    for (int i = threadIdx.x; i < FDIM * FDIM; i += blockDim.x) Ws[i] = W[i];
    __syncthreads();

    int r = blockIdx.x * blockDim.x + threadIdx.x;
    if (r >= n) return;

    unsigned long long acc2[FDIM / 2];
#pragma unroll
    for (int j = 0; j < FDIM / 2; j++) acc2[j] = 0ull;

    const float4* x4 = (const float4*)(in + (size_t)r * FDIM);
#pragma unroll 4
    for (int k4 = 0; k4 < FDIM / 4; k4++) {
        float4 xv = __ldg(x4 + k4);
        float xs[4] = {xv.x, xv.y, xv.z, xv.w};
#pragma unroll
        for (int kk = 0; kk < 4; kk++) {
            float xk = xs[kk];
            if (LRELU) xk = xk > 0.0f ? xk : 0.01f * xk;
            unsigned long long xk2 = pack2(xk);
            const ulonglong2* Wr = (const ulonglong2*)&Ws[(k4 * 4 + kk) * FDIM];
#pragma unroll
            for (int j = 0; j < FDIM / 4; j++) {
                ulonglong2 w2 = Wr[j];
                acc2[2 * j]     = ffma2(xk2, w2.x, acc2[2 * j]);
                acc2[2 * j + 1] = ffma2(xk2, w2.y, acc2[2 * j + 1]);
            }
        }
    }

    uint4* hr = (uint4*)(h + (size_t)r * FDIM);
#pragma unroll
    for (int j = 0; j < 8; j++) {
        float2 p0 = unpack2(acc2[4 * j + 0]);
        float2 p1 = unpack2(acc2[4 * j + 1]);
        float2 p2 = unpack2(acc2[4 * j + 2]);
        float2 p3 = unpack2(acc2[4 * j + 3]);
        uint4 v;
        v.x = h2_as_u32(__floats2half2_rn(p0.x, p0.y));
        v.y = h2_as_u32(__floats2half2_rn(p1.x, p1.y));
        v.z = h2_as_u32(__floats2half2_rn(p2.x, p2.y));
        v.w = h2_as_u32(__floats2half2_rn(p3.x, p3.y));
        hr[j] = v;
    }
}

// --- CSR gather: 16 lanes/node, lane owns 4 cols (uint2 = 4 halves = 8B).
//     R12 loop, untouched (5 restructures all regressed).
__device__ __forceinline__ void acc_u2(uint2 u, float nn, float4& a) {
    __half2 h0 = *reinterpret_cast<__half2*>(&u.x);
    __half2 h1 = *reinterpret_cast<__half2*>(&u.y);
    float2 f0 = __half22float2(h0);
    float2 f1 = __half22float2(h1);
    a.x = fmaf(f0.x, nn, a.x); a.y = fmaf(f0.y, nn, a.y);
    a.z = fmaf(f1.x, nn, a.z); a.w = fmaf(f1.y, nn, a.w);
}

__global__ void __launch_bounds__(256)
k_gather(const __half* __restrict__ h, float* __restrict__ out,
         const float* __restrict__ b, int n) {
    int node = blockIdx.x * 16 + (threadIdx.x >> 4);
    if (node >= n) return;
    int l16 = threadIdx.x & 15;              // owns cols [4*l16, 4*l16+4)

    const uint2* h2 = (const uint2*)h;       // 16 uint2 per row
    int start = g_row[node];
    int deg   = g_cnt[node];
    float di  = g_dinv[node];
    float sn  = di * di;

    float4 a = __ldg((const float4*)b + l16);
    acc_u2(h2[(size_t)node * 16 + l16], sn, a);   // self loop

    const int2* ed = g_edata + start;
    int e = 0;
    for (; e + 4 <= deg; e += 4) {
        int2 e0 = ed[e], e1 = ed[e + 1], e2 = ed[e + 2], e3 = ed[e + 3];
        uint2 v0 = h2[(size_t)e0.x * 16 + l16];
        uint2 v1 = h2[(size_t)e1.x * 16 + l16];
        uint2 v2 = h2[(size_t)e2.x * 16 + l16];
        uint2 v3 = h2[(size_t)e3.x * 16 + l16];
        acc_u2(v0, __int_as_float(e0.y), a);
        acc_u2(v1, __int_as_float(e1.y), a);
        acc_u2(v2, __int_as_float(e2.y), a);
        acc_u2(v3, __int_as_float(e3.y), a);
    }
    for (; e < deg; e++) {
        int2 ee = ed[e];
        uint2 v = h2[(size_t)ee.x * 16 + l16];
        acc_u2(v, __int_as_float(ee.y), a);
    }

    ((float4*)out)[(size_t)node * 16 + l16] = a;
}

extern "C" void kernel_launch(void* const* d_in, const int* in_sizes, int n_in,
                              void* d_out, int out_size) {
    const float* x  = (const float*)d_in[0];
    const void*  ei = d_in[1];
    const float* W1 = (const float*)d_in[2];
    const float* b1 = (const float*)d_in[3];
    const float* W2 = (const float*)d_in[4];
    const float* b2 = (const float*)d_in[5];
    const float* W3 = (const float*)d_in[6];
    const float* b3 = (const float*)d_in[7];
    float* out = (float*)d_out;

    int n = in_sizes[0] / FDIM;
    long long E = (long long)in_sizes[1] / 2;

    __half* hbuf;
    float* accbuf;
    cudaGetSymbolAddress((void**)&hbuf, g_h);
    cudaGetSymbolAddress((void**)&accbuf, g_acc);

    int nb_n  = (n + 255) / 256;
    int nb_e  = (int)((E + 255) / 256);
    int nb_g  = (n + 127) / 128;
    int nb_ga = (n + 15) / 16;

    k_prep0<<<nb_n, 256>>>((const unsigned int*)ei, 2 * E, n);  // 0
    k_deg<<<nb_e, 256>>>(ei, E);                                // 1
    k_dinv_alloc<<<nb_n, 256>>>(n);                             // 2
    k_fill<<<nb_e, 256>>>(ei, E);                               // 3 <- profiled
    k_gemm<0><<<nb_g, 128>>>(x, W1, hbuf, n);                   // 4
    k_gather<<<nb_ga, 256>>>(hbuf, accbuf, b1, n);              // 5
    k_gemm<1><<<nb_g, 128>>>(accbuf, W2, hbuf, n);              // 6
    k_gather<<<nb_ga, 256>>>(hbuf, accbuf, b2, n);              // 7
    k_gemm<1><<<nb_g, 128>>>(accbuf, W3, hbuf, n);              // 8
    k_gather<<<nb_ga, 256>>>(hbuf, out, b3, n);                 // 9
}

// round 17
// speedup vs baseline: 1.0659x; 1.0085x over previous
#include <cuda_runtime.h>
#include <cuda_fp16.h>
#include <cstdint>

// ---------------------------------------------------------------------------
// SimpleGCN on B200, round 17: R16 (281us best) + fp16 intermediate acts.
//   Middle gathers apply lrelu in-epilogue and store fp16 (was fp32 acc);
//   gemm2/3 consume fp16 rows. Saves ~52MB round-trip. Gather loop, gemm
//   inner loop, prep all frozen (R16 structure).
//   rel_err expected ~1e-4 (one extra fp16 quantize per middle layer).
// ---------------------------------------------------------------------------

#define MAXN (1 << 17)
#define MAXE (1 << 21)
#define FDIM 64

__device__ __half g_h [(size_t)MAXN * FDIM];     // gemm outputs (fp16)
__device__ __half g_hB[(size_t)MAXN * FDIM];     // gather outputs (fp16, lrelu'd)
__device__ float  g_dinv[MAXN];
__device__ int    g_cnt[MAXN];
__device__ int    g_row[MAXN];
__device__ int    g_cur[MAXN];
__device__ int    g_total;
__device__ int2   g_edata[MAXE];
__device__ int    g_is64;

// --- packed f32x2 helpers ---
__device__ __forceinline__ unsigned long long ffma2(
    unsigned long long a, unsigned long long b, unsigned long long c) {
    unsigned long long d;
    asm("fma.rn.f32x2 %0, %1, %2, %3;" : "=l"(d) : "l"(a), "l"(b), "l"(c));
    return d;
}
__device__ __forceinline__ unsigned long long pack2(float x) {
    unsigned long long p;
    asm("mov.b64 %0, {%1, %1};" : "=l"(p) : "f"(x));
    return p;
}
__device__ __forceinline__ float2 unpack2(unsigned long long p) {
    float lo, hi;
    asm("mov.b64 {%0, %1}, %2;" : "=f"(lo), "=f"(hi) : "l"(p));
    return make_float2(lo, hi);
}
__device__ __forceinline__ uint32_t h2_as_u32(__half2 v) {
    return *reinterpret_cast<uint32_t*>(&v);
}
__device__ __forceinline__ float2 u32_as_f2(uint32_t u) {
    __half2 h = *reinterpret_cast<__half2*>(&u);
    return __half22float2(h);
}

// --- launch 0: dtype detect + zero counters
__global__ void k_prep0(const unsigned int* __restrict__ w, long long nwords, int n) {
    int i = blockIdx.x * blockDim.x + threadIdx.x;
    if (i < n) { g_cnt[i] = 0; g_cur[i] = 0; }
    if (i == 0) g_total = 0;
    if (blockIdx.x == 0) {
        __shared__ int cnt;
        if (threadIdx.x == 0) cnt = 0;
        __syncthreads();
        int zeros = 0;
        for (long long j = threadIdx.x; j < 2048 && j < nwords; j += blockDim.x)
            if ((j & 1) && w[j] == 0u) zeros++;
        atomicAdd(&cnt, zeros);
        __syncthreads();
        if (threadIdx.x == 0) g_is64 = (cnt > 512) ? 1 : 0;
    }
}

__device__ __forceinline__ int load_idx(const void* e, long long pos) {
    if (g_is64) return (int)((const long long*)e)[pos];
    return ((const int*)e)[pos];
}

// --- launch 1: in-degree histogram
__global__ void k_deg(const void* __restrict__ e, long long E) {
    long long i = (long long)blockIdx.x * blockDim.x + threadIdx.x;
    if (i >= E) return;
    atomicAdd(&g_cnt[load_idx(e, E + i)], 1);
}

// --- launch 2: dinv + disjoint range allocation via block scan
__global__ void k_dinv_alloc(int n) {
    __shared__ int sh[256];
    __shared__ int base;
    int i = blockIdx.x * 256 + threadIdx.x;
    int c = (i < n) ? g_cnt[i] : 0;
    if (i < n) g_dinv[i] = rsqrtf((float)(1 + c));   // +1 self loop

    sh[threadIdx.x] = c;
    __syncthreads();
#pragma unroll
    for (int off = 1; off < 256; off <<= 1) {
        int t = (threadIdx.x >= off) ? sh[threadIdx.x - off] : 0;
        __syncthreads();
        sh[threadIdx.x] += t;
        __syncthreads();
    }
    if (threadIdx.x == 255) base = atomicAdd(&g_total, sh[255]);
    __syncthreads();
    if (i < n) g_row[i] = base + sh[threadIdx.x] - c;
}

// --- launch 3: CSR fill {src, norm}   <- profiled slot (canary: ~35.5us)
__global__ void k_fill(const void* __restrict__ e, long long E) {
    long long i = (long long)blockIdx.x * blockDim.x + threadIdx.x;
    if (i >= E) return;
    int s, d;
    if (g_is64) {
        const long long* p = (const long long*)e;
        s = (int)p[i]; d = (int)p[E + i];
    } else {
        const int* p = (const int*)e;
        s = p[i]; d = p[E + i];
    }
    int pos = g_row[d] + atomicAdd(&g_cur[d], 1);
    g_edata[pos] = make_int2(s, __float_as_int(g_dinv[s] * g_dinv[d]));
}

// --- GEMM layer 1: fp32 input, no lrelu, fp16 out
__global__ void __launch_bounds__(128)
k_gemm_f32(const float* __restrict__ in, const float* __restrict__ W,
           __half* __restrict__ h, int n) {
    __shared__ float Ws[FDIM * FDIM];
    for (int i = threadIdx.x; i < FDIM * FDIM; i += blockDim.x) Ws[i] = W[i];
    __syncthreads();

    int r = blockIdx.x * blockDim.x + threadIdx.x;
    if (r >= n) return;

    unsigned long long acc2[FDIM / 2];
#pragma unroll
    for (int j = 0; j < FDIM / 2; j++) acc2[j] = 0ull;

    const float4* x4 = (const float4*)(in + (size_t)r * FDIM);
#pragma unroll 4
    for (int k4 = 0; k4 < FDIM / 4; k4++) {
        float4 xv = __ldg(x4 + k4);
        float xs[4] = {xv.x, xv.y, xv.z, xv.w};
#pragma unroll
        for (int kk = 0; kk < 4; kk++) {
            unsigned long long xk2 = pack2(xs[kk]);
            const ulonglong2* Wr = (const ulonglong2*)&Ws[(k4 * 4 + kk) * FDIM];
#pragma unroll
            for (int j = 0; j < FDIM / 4; j++) {
                ulonglong2 w2 = Wr[j];
                acc2[2 * j]     = ffma2(xk2, w2.x, acc2[2 * j]);
                acc2[2 * j + 1] = ffma2(xk2, w2.y, acc2[2 * j + 1]);
            }
        }
    }

    uint4* hr = (uint4*)(h + (size_t)r * FDIM);
#pragma unroll
    for (int j = 0; j < 8; j++) {
        float2 p0 = unpack2(acc2[4 * j + 0]);
        float2 p1 = unpack2(acc2[4 * j + 1]);
        float2 p2 = unpack2(acc2[4 * j + 2]);
        float2 p3 = unpack2(acc2[4 * j + 3]);
        uint4 v;
        v.x = h2_as_u32(__floats2half2_rn(p0.x, p0.y));
        v.y = h2_as_u32(__floats2half2_rn(p1.x, p1.y));
        v.z = h2_as_u32(__floats2half2_rn(p2.x, p2.y));
        v.w = h2_as_u32(__floats2half2_rn(p3.x, p3.y));
        hr[j] = v;
    }
}

// --- GEMM layers 2,3: fp16 input (lrelu pre-applied by gather), fp16 out
__global__ void __launch_bounds__(128)
k_gemm_f16(const __half* __restrict__ in, const float* __restrict__ W,
           __half* __restrict__ h, int n) {
    __shared__ float Ws[FDIM * FDIM];
    for (int i = threadIdx.x; i < FDIM * FDIM; i += blockDim.x) Ws[i] = W[i];
    __syncthreads();

    int r = blockIdx.x * blockDim.x + threadIdx.x;
    if (r >= n) return;

    unsigned long long acc2[FDIM / 2];
#pragma unroll
    for (int j = 0; j < FDIM / 2; j++) acc2[j] = 0ull;

    const uint4* x8 = (const uint4*)(in + (size_t)r * FDIM);   // 8 halves each
#pragma unroll 2
    for (int c = 0; c < 8; c++) {
        uint4 xv = __ldg(x8 + c);
        float2 f0 = u32_as_f2(xv.x), f1 = u32_as_f2(xv.y);
        float2 f2 = u32_as_f2(xv.z), f3 = u32_as_f2(xv.w);
        float xs[8] = {f0.x, f0.y, f1.x, f1.y, f2.x, f2.y, f3.x, f3.y};
#pragma unroll
        for (int kk = 0; kk < 8; kk++) {
            unsigned long long xk2 = pack2(xs[kk]);
            const ulonglong2* Wr = (const ulonglong2*)&Ws[(c * 8 + kk) * FDIM];
#pragma unroll
            for (int j = 0; j < FDIM / 4; j++) {
                ulonglong2 w2 = Wr[j];
                acc2[2 * j]     = ffma2(xk2, w2.x, acc2[2 * j]);
                acc2[2 * j + 1] = ffma2(xk2, w2.y, acc2[2 * j + 1]);
            }
        }
    }

    uint4* hr = (uint4*)(h + (size_t)r * FDIM);
#pragma unroll
    for (int j = 0; j < 8; j++) {
        float2 p0 = unpack2(acc2[4 * j + 0]);
        float2 p1 = unpack2(acc2[4 * j + 1]);
        float2 p2 = unpack2(acc2[4 * j + 2]);
        float2 p3 = unpack2(acc2[4 * j + 3]);
        uint4 v;
        v.x = h2_as_u32(__floats2half2_rn(p0.x, p0.y));
        v.y = h2_as_u32(__floats2half2_rn(p1.x, p1.y));
        v.z = h2_as_u32(__floats2half2_rn(p2.x, p2.y));
        v.w = h2_as_u32(__floats2half2_rn(p3.x, p3.y));
        hr[j] = v;
    }
}

// --- CSR gather (R12 loop frozen). MODE 0: lrelu + fp16 out (middle layers).
//     MODE 1: plain fp32 out (final layer -> d_out).
__device__ __forceinline__ void acc_u2(uint2 u, float nn, float4& a) {
    __half2 h0 = *reinterpret_cast<__half2*>(&u.x);
    __half2 h1 = *reinterpret_cast<__half2*>(&u.y);
    float2 f0 = __half22float2(h0);
    float2 f1 = __half22float2(h1);
    a.x = fmaf(f0.x, nn, a.x); a.y = fmaf(f0.y, nn, a.y);
    a.z = fmaf(f1.x, nn, a.z); a.w = fmaf(f1.y, nn, a.w);
}

template <int MODE>
__global__ void __launch_bounds__(256)
k_gather(const __half* __restrict__ h, void* __restrict__ outv,
         const float* __restrict__ b, int n) {
    int node = blockIdx.x * 16 + (threadIdx.x >> 4);
    if (node >= n) return;
    int l16 = threadIdx.x & 15;              // owns cols [4*l16, 4*l16+4)

    const uint2* h2 = (const uint2*)h;       // 16 uint2 per row
    int start = g_row[node];
    int deg   = g_cnt[node];
    float di  = g_dinv[node];
    float sn  = di * di;

    float4 a = __ldg((const float4*)b + l16);
    acc_u2(h2[(size_t)node * 16 + l16], sn, a);   // self loop

    const int2* ed = g_edata + start;
    int e = 0;
    for (; e + 4 <= deg; e += 4) {
        int2 e0 = ed[e], e1 = ed[e + 1], e2 = ed[e + 2], e3 = ed[e + 3];
        uint2 v0 = h2[(size_t)e0.x * 16 + l16];
        uint2 v1 = h2[(size_t)e1.x * 16 + l16];
        uint2 v2 = h2[(size_t)e2.x * 16 + l16];
        uint2 v3 = h2[(size_t)e3.x * 16 + l16];
        acc_u2(v0, __int_as_float(e0.y), a);
        acc_u2(v1, __int_as_float(e1.y), a);
        acc_u2(v2, __int_as_float(e2.y), a);
        acc_u2(v3, __int_as_float(e3.y), a);
    }
    for (; e < deg; e++) {
        int2 ee = ed[e];
        uint2 v = h2[(size_t)ee.x * 16 + l16];
        acc_u2(v, __int_as_float(ee.y), a);
    }

    if (MODE == 0) {                         // lrelu + fp16
        a.x = a.x > 0.f ? a.x : 0.01f * a.x;
        a.y = a.y > 0.f ? a.y : 0.01f * a.y;
        a.z = a.z > 0.f ? a.z : 0.01f * a.z;
        a.w = a.w > 0.f ? a.w : 0.01f * a.w;
        uint2 v;
        v.x = h2_as_u32(__floats2half2_rn(a.x, a.y));
        v.y = h2_as_u32(__floats2half2_rn(a.z, a.w));
        ((uint2*)outv)[(size_t)node * 16 + l16] = v;
    } else {
        ((float4*)outv)[(size_t)node * 16 + l16] = a;
    }
}

extern "C" void kernel_launch(void* const* d_in, const int* in_sizes, int n_in,
                              void* d_out, int out_size) {
    const float* x  = (const float*)d_in[0];
    const void*  ei = d_in[1];
    const float* W1 = (const float*)d_in[2];
    const float* b1 = (const float*)d_in[3];
    const float* W2 = (const float*)d_in[4];
    const float* b2 = (const float*)d_in[5];
    const float* W3 = (const float*)d_in[6];
    const float* b3 = (const float*)d_in[7];
    float* out = (float*)d_out;

    int n = in_sizes[0] / FDIM;
    long long E = (long long)in_sizes[1] / 2;

    __half *hA, *hB;
    cudaGetSymbolAddress((void**)&hA, g_h);
    cudaGetSymbolAddress((void**)&hB, g_hB);

    int nb_n  = (n + 255) / 256;
    int nb_e  = (int)((E + 255) / 256);
    int nb_g  = (n + 127) / 128;
    int nb_ga = (n + 15) / 16;

    k_prep0<<<nb_n, 256>>>((const unsigned int*)ei, 2 * E, n);  // 0
    k_deg<<<nb_e, 256>>>(ei, E);                                // 1
    k_dinv_alloc<<<nb_n, 256>>>(n);                             // 2
    k_fill<<<nb_e, 256>>>(ei, E);                               // 3 <- profiled
    k_gemm_f32<<<nb_g, 128>>>(x, W1, hA, n);                    // 4
    k_gather<0><<<nb_ga, 256>>>(hA, hB, b1, n);                 // 5 lrelu+fp16
    k_gemm_f16<<<nb_g, 128>>>(hB, W2, hA, n);                   // 6
    k_gather<0><<<nb_ga, 256>>>(hA, hB, b2, n);                 // 7 lrelu+fp16
    k_gemm_f16<<<nb_g, 128>>>(hB, W3, hA, n);                   // 8
    k_gather<1><<<nb_ga, 256>>>(hA, out, b3, n);                // 9 fp32 out
}